// round 4
// baseline (speedup 1.0000x reference)
#include <cuda_runtime.h>
#include <math.h>
#include <stdint.h>

#define Vn 65536
#define En 262144
#define Gn 2048
#define NPG 32
#define H 200
#define DEG 4
#define NODE_IN 74
#define EDGE_IN 12
#define NLAYERS 5
#define TT 2
#define H3 600
#define H2 400

#define KT 25           // k-tiles of 8 (K=200)
#define NT 25           // n-tiles of 8 (N=200)
#define NTG 5           // nt per group (L1-resident B working set)
#define NGRP 5          // number of nt groups
#define MB 64           // rows per block (2 graphs)
#define AGG_S 204       // padded stride for s_agg

// ---------------- device scratch ----------------
__device__ float g_h[Vn * H];        // node hidden states [V,H]
__device__ float g_eh[En * H];       // edge embeddings   [E,H]
__device__ float g_gf[Gn * H];       // graph features [G,H]
__device__ float g_a[Vn];            // readout attention per node
__device__ float g_hbar[Gn * H];     // sum_v a_v * h_v per graph
__device__ float g_ctx[Gn * H];      // elu(hbar @ prW + prb)
__device__ float g_gi[Gn * H3];      // GRU input gates
__device__ float g_gh[Gn * H3];      // GRU hidden gates
__device__ float g_WihT[TT][H * H3];
__device__ float g_WhhT[TT][H * H3];
// prepacked gnn_W fragments: [layer][kt][nt][lane] = (bhi0, bhi1, blo0, blo1)
__device__ uint4 g_Bpack[NLAYERS * KT * NT * 32];

// ---------------- tf32 helpers ----------------
__device__ __forceinline__ uint32_t f2tf32(float f) {
    uint32_t r;
    asm("cvt.rna.tf32.f32 %0, %1;" : "=r"(r) : "f"(f));
    return r;
}
__device__ __forceinline__ void mma_tf32(float* c, const uint32_t* a,
                                         uint32_t b0, uint32_t b1) {
    asm volatile(
        "mma.sync.aligned.m16n8k8.row.col.f32.tf32.tf32.f32 "
        "{%0,%1,%2,%3}, {%4,%5,%6,%7}, {%8,%9}, {%0,%1,%2,%3};"
        : "+f"(c[0]), "+f"(c[1]), "+f"(c[2]), "+f"(c[3])
        : "r"(a[0]), "r"(a[1]), "r"(a[2]), "r"(a[3]), "r"(b0), "r"(b1));
}

// ---------------- prepack gnn weights into tf32 hi/lo fragment order ----------------
__global__ void k_prep(const float* __restrict__ gnn_W) {
    int idx = blockIdx.x * blockDim.x + threadIdx.x;
    if (idx >= NLAYERS * KT * NT * 32) return;
    int lane = idx & 31;
    int r = idx >> 5;
    int nt = r % NT;
    int r2 = r / NT;
    int kt = r2 % KT;
    int l = r2 / KT;
    int k0 = kt * 8 + (lane & 3);
    int n = nt * 8 + (lane >> 2);
    float w0 = gnn_W[l * H * H + k0 * H + n];
    float w1 = gnn_W[l * H * H + (k0 + 4) * H + n];
    uint32_t hi0 = f2tf32(w0);
    uint32_t hi1 = f2tf32(w1);
    uint32_t lo0 = f2tf32(w0 - __uint_as_float(hi0));
    uint32_t lo1 = f2tf32(w1 - __uint_as_float(hi1));
    uint4 p;
    p.x = hi0; p.y = hi1; p.z = lo0; p.w = lo1;
    g_Bpack[idx] = p;
}

// ---------------- transpose GRU weights ----------------
__global__ void k_transpose(const float* __restrict__ W_ih,
                            const float* __restrict__ W_hh) {
    int idx = blockIdx.x * blockDim.x + threadIdx.x;
    if (idx < TT * H3 * H) {
        int t = idx / (H3 * H);
        int r = idx - t * (H3 * H);
        int j = r / H, k = r - j * H;
        g_WihT[t][k * H3 + j] = W_ih[idx];
        g_WhhT[t][k * H3 + j] = W_hh[idx];
    }
}

// ---------------- node embedding (float2 smem reads) ----------------
__global__ __launch_bounds__(200) void k_node_embed(const float* __restrict__ nf,
                                                    const float* __restrict__ W,
                                                    const float* __restrict__ b) {
    __shared__ __align__(8) float s[32][NODE_IN];
    int v0 = blockIdx.x * 32;
    int tid = threadIdx.x;
    for (int i = tid; i < 32 * NODE_IN; i += 200) {
        int r = i / NODE_IN, k = i - r * NODE_IN;
        s[r][k] = nf[(v0 + r) * NODE_IN + k];
    }
    __syncthreads();
    int c = tid;
    float acc[32];
#pragma unroll
    for (int r = 0; r < 32; r++) acc[r] = 0.f;
    for (int k = 0; k < NODE_IN; k += 2) {
        float w0 = W[k * H + c];
        float w1 = W[(k + 1) * H + c];
#pragma unroll
        for (int r = 0; r < 32; r++) {
            float2 a = *(const float2*)&s[r][k];
            acc[r] += a.x * w0 + a.y * w1;
        }
    }
    float bb = b[c];
#pragma unroll
    for (int r = 0; r < 32; r++) g_h[(v0 + r) * H + c] = acc[r] + bb;
}

// ---------------- edge embedding (float4 smem reads) ----------------
__global__ __launch_bounds__(200) void k_edge_embed(const float* __restrict__ ef,
                                                    const float* __restrict__ W,
                                                    const float* __restrict__ b) {
    __shared__ __align__(16) float s[32][EDGE_IN];
    int e0 = blockIdx.x * 32;
    int tid = threadIdx.x;
    for (int i = tid; i < 32 * EDGE_IN; i += 200) {
        int r = i / EDGE_IN, k = i - r * EDGE_IN;
        s[r][k] = ef[(e0 + r) * EDGE_IN + k];
    }
    __syncthreads();
    int c = tid;
    float acc[32];
#pragma unroll
    for (int r = 0; r < 32; r++) acc[r] = 0.f;
#pragma unroll
    for (int k = 0; k < EDGE_IN; k += 4) {
        float w0 = W[k * H + c];
        float w1 = W[(k + 1) * H + c];
        float w2 = W[(k + 2) * H + c];
        float w3 = W[(k + 3) * H + c];
#pragma unroll
        for (int r = 0; r < 32; r++) {
            float4 a = *(const float4*)&s[r][k];
            acc[r] += a.x * w0 + a.y * w1 + a.z * w2 + a.w * w3;
        }
    }
    float bb = b[c];
#pragma unroll
    for (int r = 0; r < 32; r++) g_eh[(e0 + r) * H + c] = acc[r] + bb;
}

// ---------------- fused layer: edge-softmax agg + tf32 tensor-core update ----------------
// block = 64 nodes (2 graphs), 128 threads (4 warps, warp w -> rows [16w,16w+16))
__global__ __launch_bounds__(128, 2) void k_layer(const int* __restrict__ src,
                                                  const float* __restrict__ bias,
                                                  int layer) {
    extern __shared__ float smem[];
    float* s_h = smem;                       // [64][200]
    float* s_agg = s_h + MB * H;             // [64][204]
    int* s_src = (int*)(s_agg + MB * AGG_S); // [256]
    float* s_bias = (float*)(s_src + MB * DEG);

    int tid = threadIdx.x;
    int b = blockIdx.x;
    int vbase = b * MB;

    // phase 1: stage h, src, bias
    {
        const float4* gsrc = (const float4*)(g_h + vbase * H);
        float4* dst = (float4*)s_h;
#pragma unroll
        for (int i = 0; i < (MB * H / 4) / 128; i++) dst[tid + i * 128] = gsrc[tid + i * 128];
        {
            int2 sp = ((const int2*)(src + b * MB * DEG))[tid];
            s_src[tid * 2] = sp.x - vbase;
            s_src[tid * 2 + 1] = sp.y - vbase;
        }
        for (int i = tid; i < H; i += 128) s_bias[i] = bias[i];
    }
    __syncthreads();

    // phase 2: per-element edge softmax + aggregation -> s_agg
    {
        const float* ehb = g_eh + (size_t)b * (MB * DEG) * H;
        for (int i = tid; i < MB * H; i += 128) {
            int v = i / H;
            int k = i - v * H;
            int e0 = v * DEG;
            float m0 = s_h[s_src[e0 + 0] * H + k] + __ldg(&ehb[(e0 + 0) * H + k]);
            float m1 = s_h[s_src[e0 + 1] * H + k] + __ldg(&ehb[(e0 + 1) * H + k]);
            float m2 = s_h[s_src[e0 + 2] * H + k] + __ldg(&ehb[(e0 + 2) * H + k]);
            float m3 = s_h[s_src[e0 + 3] * H + k] + __ldg(&ehb[(e0 + 3) * H + k]);
            float mx = fmaxf(fmaxf(m0, m1), fmaxf(m2, m3));
            float e0x = __expf(m0 - mx), e1x = __expf(m1 - mx);
            float e2x = __expf(m2 - mx), e3x = __expf(m3 - mx);
            float den = e0x + e1x + e2x + e3x;
            float agg = m0 * e0x + m1 * e1x + m2 * e2x + m3 * e3x;
            s_agg[v * AGG_S + k] = agg / den;
        }
    }
    __syncthreads();

    // phase 3+4: D = agg @ W (3xTF32) processed in 5 nt-groups of 5
    // (per-group B working set = 25kt*5nt*512B = 64 KB -> L1-resident,
    //  shared across warps / resident blocks / successive CTAs on the SM)
    int warp = tid >> 5;
    int lane = tid & 31;
    int m0 = warp * 16;
    int gr = lane >> 2;   // group id (row within fragment)
    int tg = lane & 3;    // thread in group

    const uint4* bpl = g_Bpack + (size_t)layer * KT * NT * 32 + lane;

    for (int gidx = 0; gidx < NGRP; gidx++) {
        float cA[NTG][4], cB[NTG][4];
#pragma unroll
        for (int j = 0; j < NTG; j++) {
            cA[j][0] = 0.f; cA[j][1] = 0.f; cA[j][2] = 0.f; cA[j][3] = 0.f;
            cB[j][0] = 0.f; cB[j][1] = 0.f; cB[j][2] = 0.f; cB[j][3] = 0.f;
        }
        const uint4* bpg = bpl + (size_t)(gidx * NTG) * 32;
        for (int kt = 0; kt < KT; kt++) {
            int k0 = kt * 8 + tg;
            float a0f = s_agg[(m0 + gr) * AGG_S + k0];
            float a1f = s_agg[(m0 + gr + 8) * AGG_S + k0];
            float a2f = s_agg[(m0 + gr) * AGG_S + k0 + 4];
            float a3f = s_agg[(m0 + gr + 8) * AGG_S + k0 + 4];
            uint32_t ahi[4], alo[4];
            ahi[0] = f2tf32(a0f); alo[0] = f2tf32(a0f - __uint_as_float(ahi[0]));
            ahi[1] = f2tf32(a1f); alo[1] = f2tf32(a1f - __uint_as_float(ahi[1]));
            ahi[2] = f2tf32(a2f); alo[2] = f2tf32(a2f - __uint_as_float(ahi[2]));
            ahi[3] = f2tf32(a3f); alo[3] = f2tf32(a3f - __uint_as_float(ahi[3]));
            const uint4* bp = bpg + (size_t)kt * NT * 32;
#pragma unroll
            for (int j = 0; j < NTG; j++) {
                uint4 p = __ldg(&bp[j * 32]);
                mma_tf32(cA[j], ahi, p.x, p.y);   // Ahi*Bhi  (chain A)
                mma_tf32(cB[j], ahi, p.z, p.w);   // Ahi*Blo  (chain B)
                mma_tf32(cB[j], alo, p.x, p.y);   // Alo*Bhi  (chain B)
            }
        }
        // writeback this group: h = relu(D + bias) + h_old
        int r0 = m0 + gr;
        int r1 = r0 + 8;
#pragma unroll
        for (int j = 0; j < NTG; j++) {
            int n0 = (gidx * NTG + j) * 8 + tg * 2;
            float b0v = s_bias[n0], b1v = s_bias[n0 + 1];
            float o00 = fmaxf(cA[j][0] + cB[j][0] + b0v, 0.f) + s_h[r0 * H + n0];
            float o01 = fmaxf(cA[j][1] + cB[j][1] + b1v, 0.f) + s_h[r0 * H + n0 + 1];
            float o10 = fmaxf(cA[j][2] + cB[j][2] + b0v, 0.f) + s_h[r1 * H + n0];
            float o11 = fmaxf(cA[j][3] + cB[j][3] + b1v, 0.f) + s_h[r1 * H + n0 + 1];
            *(float2*)(g_h + (size_t)(vbase + r0) * H + n0) = make_float2(o00, o01);
            *(float2*)(g_h + (size_t)(vbase + r1) * H + n0) = make_float2(o10, o11);
        }
    }
}

// ---------------- gf init ----------------
__global__ __launch_bounds__(200) void k_gf() {
    int g = blockIdx.x, c = threadIdx.x;
    float sum = 0.f;
    int base = g * NPG * H + c;
    for (int i = 0; i < NPG; i++) sum += g_h[base + i * H];
    g_gf[g * H + c] = sum;
}

// ---------------- readout attention ----------------
__global__ __launch_bounds__(256) void k_z(const float* __restrict__ lgW,
                                           const float* __restrict__ lgb, int t) {
    const float* w = lgW + t * H2;
    float bb = __ldg(&lgb[t]);
    int g = blockIdx.x;
    int tid = threadIdx.x;
    __shared__ float red[256];
    __shared__ float zs[NPG];

    float p = 0.f;
    if (tid < H) {
        float gfv = g_gf[g * H + tid];
        gfv = gfv > 0.f ? gfv : 0.f;
        p = gfv * w[tid];
    }
    red[tid] = p;
    __syncthreads();
    for (int off = 128; off > 0; off >>= 1) {
        if (tid < off) red[tid] += red[tid + off];
        __syncthreads();
    }
    float sg = red[0];

    int warp = tid >> 5, lane = tid & 31;
    for (int n = warp; n < NPG; n += 8) {
        int v = g * NPG + n;
        float sum = 0.f;
        for (int c = lane; c < H; c += 32) sum += g_h[v * H + c] * w[H + c];
        for (int off = 16; off; off >>= 1) sum += __shfl_xor_sync(0xffffffffu, sum, off);
        if (lane == 0) {
            float z = sum + sg + bb;
            zs[n] = z > 0.f ? z : 0.01f * z;
        }
    }
    __syncthreads();
    if (tid < 32) {
        float zv = zs[tid];
        float mx = zv;
        for (int off = 16; off; off >>= 1) mx = fmaxf(mx, __shfl_xor_sync(0xffffffffu, mx, off));
        float e = __expf(zv - mx);
        float den = e;
        for (int off = 16; off; off >>= 1) den += __shfl_xor_sync(0xffffffffu, den, off);
        g_a[g * NPG + tid] = e / den;
    }
}

// ---------------- hbar ----------------
__global__ __launch_bounds__(200) void k_hbar() {
    int g = blockIdx.x, c = threadIdx.x;
    float sum = 0.f;
    int vb = g * NPG;
    for (int i = 0; i < NPG; i++) sum += __ldg(&g_a[vb + i]) * g_h[(vb + i) * H + c];
    g_hbar[g * H + c] = sum;
}

// ---------------- ctx ----------------
__global__ __launch_bounds__(200) void k_ctx(const float* __restrict__ prW,
                                             const float* __restrict__ prb, int t) {
    const float* W = prW + t * H * H;
    const float* b = prb + t * H;
    __shared__ __align__(16) float s[32][H];
    int g0 = blockIdx.x * 32;
    int tid = threadIdx.x;
    for (int i = tid; i < 32 * H; i += 200) {
        int r = i / H, k = i - r * H;
        s[r][k] = g_hbar[(g0 + r) * H + k];
    }
    __syncthreads();
    int c = tid;
    float acc[32];
#pragma unroll
    for (int r = 0; r < 32; r++) acc[r] = 0.f;
    for (int k = 0; k < H; k += 4) {
        float w0 = W[k * H + c];
        float w1 = W[(k + 1) * H + c];
        float w2 = W[(k + 2) * H + c];
        float w3 = W[(k + 3) * H + c];
#pragma unroll
        for (int r = 0; r < 32; r++) {
            float4 a = *(const float4*)&s[r][k];
            acc[r] += a.x * w0 + a.y * w1 + a.z * w2 + a.w * w3;
        }
    }
    float bb = b[c];
#pragma unroll
    for (int r = 0; r < 32; r++) {
        float o = acc[r] + bb;
        o = o > 0.f ? o : expm1f(o);
        g_ctx[(g0 + r) * H + c] = o;
    }
}

// ---------------- GRU gate GEMMs ----------------
__global__ __launch_bounds__(600) void k_gru(const float* __restrict__ bih,
                                             const float* __restrict__ bhh, int t) {
    __shared__ __align__(16) float sc[16][H];
    __shared__ __align__(16) float sh[16][H];
    int g0 = blockIdx.x * 16;
    int tid = threadIdx.x;
    for (int i = tid; i < 16 * H; i += 600) {
        int r = i / H, k = i - r * H;
        sc[r][k] = g_ctx[(g0 + r) * H + k];
        sh[r][k] = g_gf[(g0 + r) * H + k];
    }
    __syncthreads();
    int j = tid;
    const float* Wi = g_WihT[t];
    const float* Wh = g_WhhT[t];
    float ai[16], ah[16];
#pragma unroll
    for (int r = 0; r < 16; r++) { ai[r] = 0.f; ah[r] = 0.f; }
    for (int k = 0; k < H; k += 4) {
        float wi0 = Wi[k * H3 + j], wi1 = Wi[(k + 1) * H3 + j];
        float wi2 = Wi[(k + 2) * H3 + j], wi3 = Wi[(k + 3) * H3 + j];
        float wh0 = Wh[k * H3 + j], wh1 = Wh[(k + 1) * H3 + j];
        float wh2 = Wh[(k + 2) * H3 + j], wh3 = Wh[(k + 3) * H3 + j];
#pragma unroll
        for (int r = 0; r < 16; r++) {
            float4 a = *(const float4*)&sc[r][k];
            ai[r] += a.x * wi0 + a.y * wi1 + a.z * wi2 + a.w * wi3;
            float4 h4 = *(const float4*)&sh[r][k];
            ah[r] += h4.x * wh0 + h4.y * wh1 + h4.z * wh2 + h4.w * wh3;
        }
    }
    float bi = bih[t * H3 + j], bh = bhh[t * H3 + j];
#pragma unroll
    for (int r = 0; r < 16; r++) {
        g_gi[(g0 + r) * H3 + j] = ai[r] + bi;
        g_gh[(g0 + r) * H3 + j] = ah[r] + bh;
    }
}

// ---------------- GRU combine ----------------
__global__ __launch_bounds__(200) void k_gate() {
    int g = blockIdx.x, c = threadIdx.x;
    int base = g * H3;
    float ir = g_gi[base + c],          hr = g_gh[base + c];
    float iz = g_gi[base + H + c],      hz = g_gh[base + H + c];
    float in_ = g_gi[base + 2 * H + c], hn = g_gh[base + 2 * H + c];
    float r = 1.f / (1.f + expf(-(ir + hr)));
    float u = 1.f / (1.f + expf(-(iz + hz)));
    float n = tanhf(in_ + r * hn);
    int o = g * H + c;
    g_gf[o] = (1.f - u) * n + u * g_gf[o];
}

// ---------------- copy result ----------------
__global__ void k_copy(float* __restrict__ out, int n) {
    int i = blockIdx.x * blockDim.x + threadIdx.x;
    if (i < n) out[i] = g_gf[i];
}

// ---------------- launcher ----------------
extern "C" void kernel_launch(void* const* d_in, const int* in_sizes, int n_in,
                              void* d_out, int out_size) {
    const float* node_feat = (const float*)d_in[0];
    const float* edge_feat = (const float*)d_in[1];
    const int*   src       = (const int*)d_in[2];
    const float* node_W = (const float*)d_in[5];
    const float* node_b = (const float*)d_in[6];
    const float* edge_W = (const float*)d_in[7];
    const float* edge_b = (const float*)d_in[8];
    const float* gnn_W  = (const float*)d_in[9];
    const float* gnn_b  = (const float*)d_in[10];
    const float* lg_W   = (const float*)d_in[11];
    const float* lg_b   = (const float*)d_in[12];
    const float* pr_W   = (const float*)d_in[13];
    const float* pr_b   = (const float*)d_in[14];
    const float* W_ih   = (const float*)d_in[15];
    const float* W_hh   = (const float*)d_in[16];
    const float* b_ih   = (const float*)d_in[17];
    const float* b_hh   = (const float*)d_in[18];

    const int SMEM_LAYER = (MB * H + MB * AGG_S + MB * DEG + H) * 4;
    cudaFuncSetAttribute(k_layer, cudaFuncAttributeMaxDynamicSharedMemorySize, SMEM_LAYER);

    k_prep<<<(NLAYERS * KT * NT * 32 + 255) / 256, 256>>>(gnn_W);
    k_transpose<<<(TT * H3 * H + 255) / 256, 256>>>(W_ih, W_hh);
    k_node_embed<<<Vn / 32, 200>>>(node_feat, node_W, node_b);
    k_edge_embed<<<En / 32, 200>>>(edge_feat, edge_W, edge_b);

    for (int i = 0; i < NLAYERS; i++) {
        k_layer<<<Vn / MB, 128, SMEM_LAYER>>>(src, gnn_b + i * H, i);
    }

    k_gf<<<Gn, 200>>>();
    for (int t = 0; t < TT; t++) {
        k_z<<<Gn, 256>>>(lg_W, lg_b, t);
        k_hbar<<<Gn, 200>>>();
        k_ctx<<<Gn / 32, 200>>>(pr_W, pr_b, t);
        k_gru<<<Gn / 16, 600>>>(b_ih, b_hh, t);
        k_gate<<<Gn, 200>>>();
    }

    k_copy<<<(Gn * H + 255) / 256, 256>>>((float*)d_out, Gn * H);
}

// round 5
// speedup vs baseline: 1.0826x; 1.0826x over previous
#include <cuda_runtime.h>
#include <math.h>
#include <stdint.h>

#define Vn 65536
#define En 262144
#define Gn 2048
#define NPG 32
#define H 200
#define DEG 4
#define NODE_IN 74
#define EDGE_IN 12
#define NLAYERS 5
#define TT 2
#define H3 600
#define H2 400

typedef unsigned long long ull;

// ---------------- device scratch ----------------
__device__ float g_h[Vn * H];        // node hidden states [V,H]
__device__ float g_eh[En * H];       // edge embeddings   [E,H]
__device__ float g_gf[Gn * H];       // graph features [G,H]
__device__ float g_a[Vn];            // readout attention per node
__device__ float g_hbar[Gn * H];     // sum_v a_v * h_v per graph
__device__ float g_ctx[Gn * H];      // elu(hbar @ prW + prb)
__device__ float g_gi[Gn * H3];      // GRU input gates
__device__ float g_gh[Gn * H3];      // GRU hidden gates
__device__ float g_WihT[TT][H * H3];
__device__ float g_WhhT[TT][H * H3];

// ---------------- packed f32x2 helpers (sm_103a FFMA2 pipe) ----------------
__device__ __forceinline__ ull pk2(float lo, float hi) {
    ull r;
    asm("mov.b64 %0, {%1, %2};" : "=l"(r) : "f"(lo), "f"(hi));
    return r;
}
__device__ __forceinline__ void fma2(ull& d, ull a, ull b) {
    asm("fma.rn.f32x2 %0, %1, %2, %0;" : "+l"(d) : "l"(a), "l"(b));
}
__device__ __forceinline__ float hsum2(ull v) {
    float x, y;
    asm("mov.b64 {%0, %1}, %2;" : "=f"(x), "=f"(y) : "l"(v));
    return x + y;
}

// ---------------- transpose GRU weights ----------------
__global__ void k_transpose(const float* __restrict__ W_ih,
                            const float* __restrict__ W_hh) {
    int idx = blockIdx.x * blockDim.x + threadIdx.x;
    if (idx < TT * H3 * H) {
        int t = idx / (H3 * H);
        int r = idx - t * (H3 * H);
        int j = r / H, k = r - j * H;
        g_WihT[t][k * H3 + j] = W_ih[idx];
        g_WhhT[t][k * H3 + j] = W_hh[idx];
    }
}

// ---------------- node embedding: h = node_feat @ node_W + node_b ----------------
__global__ __launch_bounds__(200) void k_node_embed(const float* __restrict__ nf,
                                                    const float* __restrict__ W,
                                                    const float* __restrict__ b) {
    __shared__ __align__(16) float s[32][NODE_IN];
    int v0 = blockIdx.x * 32;
    int tid = threadIdx.x;
    for (int i = tid; i < 32 * NODE_IN; i += 200) {
        int r = i / NODE_IN, k = i - r * NODE_IN;
        s[r][k] = nf[(v0 + r) * NODE_IN + k];
    }
    __syncthreads();
    int c = tid;
    ull acc[32];
#pragma unroll
    for (int r = 0; r < 32; r++) acc[r] = 0ull;
    for (int k = 0; k < NODE_IN; k += 2) {
        ull w = pk2(W[k * H + c], W[(k + 1) * H + c]);
#pragma unroll
        for (int r = 0; r < 32; r++) {
            ull a = *(const ull*)&s[r][k];   // 296B row stride, 8B aligned
            fma2(acc[r], a, w);
        }
    }
    float bb = b[c];
#pragma unroll
    for (int r = 0; r < 32; r++) g_h[(v0 + r) * H + c] = hsum2(acc[r]) + bb;
}

// ---------------- edge embedding: eh = edge_feat @ edge_W + edge_b ----------------
__global__ __launch_bounds__(200) void k_edge_embed(const float* __restrict__ ef,
                                                    const float* __restrict__ W,
                                                    const float* __restrict__ b) {
    __shared__ __align__(16) float s[32][EDGE_IN];
    int e0 = blockIdx.x * 32;
    int tid = threadIdx.x;
    for (int i = tid; i < 32 * EDGE_IN; i += 200) {
        int r = i / EDGE_IN, k = i - r * EDGE_IN;
        s[r][k] = ef[(e0 + r) * EDGE_IN + k];
    }
    __syncthreads();
    int c = tid;
    ull acc[32];
#pragma unroll
    for (int r = 0; r < 32; r++) acc[r] = 0ull;
#pragma unroll
    for (int k = 0; k < EDGE_IN; k += 4) {
        ull w01 = pk2(W[k * H + c], W[(k + 1) * H + c]);
        ull w23 = pk2(W[(k + 2) * H + c], W[(k + 3) * H + c]);
#pragma unroll
        for (int r = 0; r < 32; r++) {
            ulonglong2 a = *(const ulonglong2*)&s[r][k];  // 48B stride, 16B aligned
            fma2(acc[r], a.x, w01);
            fma2(acc[r], a.y, w23);
        }
    }
    float bb = b[c];
#pragma unroll
    for (int r = 0; r < 32; r++) g_eh[(e0 + r) * H + c] = hsum2(acc[r]) + bb;
}

// ---------------- fused layer: edge-softmax agg + FFMA2 update ----------------
// block = 1 graph (32 nodes), 200 threads (thread = output column)
__global__ __launch_bounds__(200) void k_layer(const int* __restrict__ src,
                                               const float* __restrict__ W,
                                               const float* __restrict__ bias) {
    extern __shared__ float smem[];
    float* s_h = smem;                 // [32][200]
    float* s_agg = s_h + NPG * H;      // [32][200]
    int* s_src = (int*)(s_agg + NPG * H);  // [128]

    int g = blockIdx.x;
    int tid = threadIdx.x;
    int vbase = g * NPG;

    // phase 1: stage h (coalesced float4) + src
    {
        const float4* gh4 = (const float4*)(g_h + (size_t)vbase * H);
        float4* sh4 = (float4*)s_h;
        for (int i = tid; i < NPG * H / 4; i += 200) sh4[i] = gh4[i];
        if (tid < NPG * DEG) s_src[tid] = src[vbase * DEG + tid] - vbase;
    }
    __syncthreads();

    // phase 2: per-column edge softmax + aggregation -> s_agg
    int c = tid;
    {
        const float* ehb = g_eh + (size_t)vbase * DEG * H;
#pragma unroll 4
        for (int v = 0; v < NPG; v++) {
            int e0 = v * DEG;
            float m0 = s_h[s_src[e0 + 0] * H + c] + __ldg(&ehb[(e0 + 0) * H + c]);
            float m1 = s_h[s_src[e0 + 1] * H + c] + __ldg(&ehb[(e0 + 1) * H + c]);
            float m2 = s_h[s_src[e0 + 2] * H + c] + __ldg(&ehb[(e0 + 2) * H + c]);
            float m3 = s_h[s_src[e0 + 3] * H + c] + __ldg(&ehb[(e0 + 3) * H + c]);
            float mx = fmaxf(fmaxf(m0, m1), fmaxf(m2, m3));
            float e0x = __expf(m0 - mx), e1x = __expf(m1 - mx);
            float e2x = __expf(m2 - mx), e3x = __expf(m3 - mx);
            float den = e0x + e1x + e2x + e3x;
            float agg = m0 * e0x + m1 * e1x + m2 * e2x + m3 * e3x;
            s_agg[v * H + c] = agg / den;
        }
    }
    __syncthreads();

    // phase 3: D = agg @ W via packed FFMA2, thread = column c, 32 rows
    ull acc[NPG];
#pragma unroll
    for (int r = 0; r < NPG; r++) acc[r] = 0ull;
    for (int k = 0; k < H; k += 4) {
        ull w01 = pk2(W[k * H + c], W[(k + 1) * H + c]);
        ull w23 = pk2(W[(k + 2) * H + c], W[(k + 3) * H + c]);
#pragma unroll
        for (int r = 0; r < NPG; r++) {
            ulonglong2 a = *(const ulonglong2*)&s_agg[r * H + k];  // LDS.128, broadcast
            fma2(acc[r], a.x, w01);
            fma2(acc[r], a.y, w23);
        }
    }

    // phase 4: h = relu(D + bias) + h_old
    float bb = bias[c];
#pragma unroll
    for (int r = 0; r < NPG; r++) {
        float o = hsum2(acc[r]) + bb;
        o = o > 0.f ? o : 0.f;
        g_h[(size_t)(vbase + r) * H + c] = o + s_h[r * H + c];
    }
}

// ---------------- gf init: segment_sum of h per graph ----------------
__global__ __launch_bounds__(200) void k_gf() {
    int g = blockIdx.x, c = threadIdx.x;
    float sum = 0.f;
    int base = g * NPG * H + c;
    for (int i = 0; i < NPG; i++) sum += g_h[base + i * H];
    g_gf[g * H + c] = sum;
}

// ---------------- readout attention z + per-graph softmax ----------------
__global__ __launch_bounds__(256) void k_z(const float* __restrict__ lgW,
                                           const float* __restrict__ lgb, int t) {
    const float* w = lgW + t * H2;
    float bb = __ldg(&lgb[t]);
    int g = blockIdx.x;
    int tid = threadIdx.x;
    __shared__ float red[256];
    __shared__ float zs[NPG];

    float p = 0.f;
    if (tid < H) {
        float gfv = g_gf[g * H + tid];
        gfv = gfv > 0.f ? gfv : 0.f;
        p = gfv * w[tid];
    }
    red[tid] = p;
    __syncthreads();
    for (int off = 128; off > 0; off >>= 1) {
        if (tid < off) red[tid] += red[tid + off];
        __syncthreads();
    }
    float sg = red[0];

    int warp = tid >> 5, lane = tid & 31;
    for (int n = warp; n < NPG; n += 8) {
        int v = g * NPG + n;
        float sum = 0.f;
        for (int c = lane; c < H; c += 32) sum += g_h[v * H + c] * w[H + c];
        for (int off = 16; off; off >>= 1) sum += __shfl_xor_sync(0xffffffffu, sum, off);
        if (lane == 0) {
            float z = sum + sg + bb;
            zs[n] = z > 0.f ? z : 0.01f * z;
        }
    }
    __syncthreads();
    if (tid < 32) {
        float zv = zs[tid];
        float mx = zv;
        for (int off = 16; off; off >>= 1) mx = fmaxf(mx, __shfl_xor_sync(0xffffffffu, mx, off));
        float e = __expf(zv - mx);
        float den = e;
        for (int off = 16; off; off >>= 1) den += __shfl_xor_sync(0xffffffffu, den, off);
        g_a[g * NPG + tid] = e / den;
    }
}

// ---------------- hbar = sum_v a_v * h_v per graph ----------------
__global__ __launch_bounds__(200) void k_hbar() {
    int g = blockIdx.x, c = threadIdx.x;
    float sum = 0.f;
    int vb = g * NPG;
    for (int i = 0; i < NPG; i++) sum += __ldg(&g_a[vb + i]) * g_h[(vb + i) * H + c];
    g_hbar[g * H + c] = sum;
}

// ---------------- ctx = elu(hbar @ prW + prb)  [2048,200]x[200,200] ----------------
__global__ __launch_bounds__(200) void k_ctx(const float* __restrict__ prW,
                                             const float* __restrict__ prb, int t) {
    const float* W = prW + t * H * H;
    const float* b = prb + t * H;
    __shared__ __align__(16) float s[32][H];
    int g0 = blockIdx.x * 32;
    int tid = threadIdx.x;
    for (int i = tid; i < 32 * H; i += 200) {
        int r = i / H, k = i - r * H;
        s[r][k] = g_hbar[(g0 + r) * H + k];
    }
    __syncthreads();
    int c = tid;
    ull acc[32];
#pragma unroll
    for (int r = 0; r < 32; r++) acc[r] = 0ull;
    for (int k = 0; k < H; k += 4) {
        ull w01 = pk2(W[k * H + c], W[(k + 1) * H + c]);
        ull w23 = pk2(W[(k + 2) * H + c], W[(k + 3) * H + c]);
#pragma unroll
        for (int r = 0; r < 32; r++) {
            ulonglong2 a = *(const ulonglong2*)&s[r][k];
            fma2(acc[r], a.x, w01);
            fma2(acc[r], a.y, w23);
        }
    }
    float bb = b[c];
#pragma unroll
    for (int r = 0; r < 32; r++) {
        float o = hsum2(acc[r]) + bb;
        o = o > 0.f ? o : expm1f(o);
        g_ctx[(g0 + r) * H + c] = o;
    }
}

// ---------------- GRU gate GEMMs ----------------
__global__ __launch_bounds__(600) void k_gru(const float* __restrict__ bih,
                                             const float* __restrict__ bhh, int t) {
    __shared__ __align__(16) float sc[16][H];
    __shared__ __align__(16) float sh[16][H];
    int g0 = blockIdx.x * 16;
    int tid = threadIdx.x;
    for (int i = tid; i < 16 * H; i += 600) {
        int r = i / H, k = i - r * H;
        sc[r][k] = g_ctx[(g0 + r) * H + k];
        sh[r][k] = g_gf[(g0 + r) * H + k];
    }
    __syncthreads();
    int j = tid;
    const float* Wi = g_WihT[t];
    const float* Wh = g_WhhT[t];
    ull ai[16], ah[16];
#pragma unroll
    for (int r = 0; r < 16; r++) { ai[r] = 0ull; ah[r] = 0ull; }
    for (int k = 0; k < H; k += 4) {
        ull wi01 = pk2(Wi[k * H3 + j], Wi[(k + 1) * H3 + j]);
        ull wi23 = pk2(Wi[(k + 2) * H3 + j], Wi[(k + 3) * H3 + j]);
        ull wh01 = pk2(Wh[k * H3 + j], Wh[(k + 1) * H3 + j]);
        ull wh23 = pk2(Wh[(k + 2) * H3 + j], Wh[(k + 3) * H3 + j]);
#pragma unroll
        for (int r = 0; r < 16; r++) {
            ulonglong2 a = *(const ulonglong2*)&sc[r][k];
            fma2(ai[r], a.x, wi01);
            fma2(ai[r], a.y, wi23);
            ulonglong2 h4 = *(const ulonglong2*)&sh[r][k];
            fma2(ah[r], h4.x, wh01);
            fma2(ah[r], h4.y, wh23);
        }
    }
    float bi = bih[t * H3 + j], bh = bhh[t * H3 + j];
#pragma unroll
    for (int r = 0; r < 16; r++) {
        g_gi[(g0 + r) * H3 + j] = hsum2(ai[r]) + bi;
        g_gh[(g0 + r) * H3 + j] = hsum2(ah[r]) + bh;
    }
}

// ---------------- GRU combine ----------------
__global__ __launch_bounds__(200) void k_gate() {
    int g = blockIdx.x, c = threadIdx.x;
    int base = g * H3;
    float ir = g_gi[base + c],          hr = g_gh[base + c];
    float iz = g_gi[base + H + c],      hz = g_gh[base + H + c];
    float in_ = g_gi[base + 2 * H + c], hn = g_gh[base + 2 * H + c];
    float r = 1.f / (1.f + expf(-(ir + hr)));
    float u = 1.f / (1.f + expf(-(iz + hz)));
    float n = tanhf(in_ + r * hn);
    int o = g * H + c;
    g_gf[o] = (1.f - u) * n + u * g_gf[o];
}

// ---------------- copy result ----------------
__global__ void k_copy(float* __restrict__ out, int n) {
    int i = blockIdx.x * blockDim.x + threadIdx.x;
    if (i < n) out[i] = g_gf[i];
}

// ---------------- launcher ----------------
extern "C" void kernel_launch(void* const* d_in, const int* in_sizes, int n_in,
                              void* d_out, int out_size) {
    const float* node_feat = (const float*)d_in[0];
    const float* edge_feat = (const float*)d_in[1];
    const int*   src       = (const int*)d_in[2];
    const float* node_W = (const float*)d_in[5];
    const float* node_b = (const float*)d_in[6];
    const float* edge_W = (const float*)d_in[7];
    const float* edge_b = (const float*)d_in[8];
    const float* gnn_W  = (const float*)d_in[9];
    const float* gnn_b  = (const float*)d_in[10];
    const float* lg_W   = (const float*)d_in[11];
    const float* lg_b   = (const float*)d_in[12];
    const float* pr_W   = (const float*)d_in[13];
    const float* pr_b   = (const float*)d_in[14];
    const float* W_ih   = (const float*)d_in[15];
    const float* W_hh   = (const float*)d_in[16];
    const float* b_ih   = (const float*)d_in[17];
    const float* b_hh   = (const float*)d_in[18];

    const int SMEM_LAYER = (2 * NPG * H + NPG * DEG) * 4;  // ~52KB
    cudaFuncSetAttribute(k_layer, cudaFuncAttributeMaxDynamicSharedMemorySize, SMEM_LAYER);

    k_transpose<<<(TT * H3 * H + 255) / 256, 256>>>(W_ih, W_hh);
    k_node_embed<<<Vn / 32, 200>>>(node_feat, node_W, node_b);
    k_edge_embed<<<En / 32, 200>>>(edge_feat, edge_W, edge_b);

    for (int i = 0; i < NLAYERS; i++) {
        k_layer<<<Gn, 200, SMEM_LAYER>>>(src, gnn_W + i * H * H, gnn_b + i * H);
    }

    k_gf<<<Gn, 200>>>();
    for (int t = 0; t < TT; t++) {
        k_z<<<Gn, 256>>>(lg_W, lg_b, t);
        k_hbar<<<Gn, 200>>>();
        k_ctx<<<Gn / 32, 200>>>(pr_W, pr_b, t);
        k_gru<<<Gn / 16, 600>>>(b_ih, b_hh, t);
        k_gate<<<Gn, 200>>>();
    }

    k_copy<<<(Gn * H + 255) / 256, 256>>>((float*)d_out, Gn * H);
}

// round 6
// speedup vs baseline: 1.2828x; 1.1850x over previous
#include <cuda_runtime.h>
#include <math.h>
#include <stdint.h>

#define Vn 65536
#define En 262144
#define Gn 2048
#define NPG 32
#define H 200
#define DEG 4
#define NODE_IN 74
#define EDGE_IN 12
#define NLAYERS 5
#define TT 2
#define H3 600
#define H2 400

typedef unsigned long long ull;

// ---------------- device scratch ----------------
__device__ float g_h[Vn * H];
__device__ float g_eh[En * H];
__device__ float g_gf[Gn * H];
__device__ float g_a[Vn];
__device__ float g_hbar[Gn * H];
__device__ float g_ctx[Gn * H];
__device__ float g_gi[Gn * H3];
__device__ float g_gh[Gn * H3];
// packed-pair weights: out[k2*N + n] = (W[2k2][n], W[2k2+1][n])
__device__ ull g_Wgnn[NLAYERS * 100 * H];   // 5 layers, K=200 -> 100 pairs
__device__ ull g_Wpr[TT * 100 * H];
__device__ ull g_Wnode[37 * H];             // K=74 -> 37 pairs
__device__ ull g_Wedge[6 * H];              // K=12 -> 6 pairs
__device__ ull g_Wih2[TT * 100 * H3];       // transposed+packed GRU weights
__device__ ull g_Whh2[TT * 100 * H3];

// ---------------- packed f32x2 helpers ----------------
__device__ __forceinline__ ull pk2(float lo, float hi) {
    ull r;
    asm("mov.b64 %0, {%1, %2};" : "=l"(r) : "f"(lo), "f"(hi));
    return r;
}
__device__ __forceinline__ void fma2(ull& d, ull a, ull b) {
    asm("fma.rn.f32x2 %0, %1, %2, %0;" : "+l"(d) : "l"(a), "l"(b));
}
__device__ __forceinline__ float hsum2(ull v) {
    float x, y;
    asm("mov.b64 {%0, %1}, %2;" : "=f"(x), "=f"(y) : "l"(v));
    return x + y;
}

// ---------------- weight packing ----------------
__global__ void k_packW(const float* __restrict__ W, ull* __restrict__ out,
                        int K2, int N) {
    int idx = blockIdx.x * blockDim.x + threadIdx.x;
    if (idx < K2 * N) {
        int k2 = idx / N, n = idx - k2 * N;
        out[idx] = pk2(W[(2 * k2) * N + n], W[(2 * k2 + 1) * N + n]);
    }
}
__global__ void k_packGRU(const float* __restrict__ W_ih,
                          const float* __restrict__ W_hh) {
    int idx = blockIdx.x * blockDim.x + threadIdx.x;
    if (idx < TT * 100 * H3) {
        int t = idx / (100 * H3);
        int r = idx - t * (100 * H3);
        int k2 = r / H3, j = r - k2 * H3;
        const float* wi = W_ih + t * H3 * H + j * H + 2 * k2;
        const float* wh = W_hh + t * H3 * H + j * H + 2 * k2;
        g_Wih2[idx] = pk2(wi[0], wi[1]);
        g_Whh2[idx] = pk2(wh[0], wh[1]);
    }
}

// ---------------- node embedding: 400 threads, 2 row-groups x 200 cols ----------------
__global__ __launch_bounds__(400, 2) void k_node_embed(const float* __restrict__ nf,
                                                       const float* __restrict__ b) {
    __shared__ __align__(16) float s[32][NODE_IN];
    int v0 = blockIdx.x * 32;
    int tid = threadIdx.x;
    for (int i = tid; i < 32 * NODE_IN; i += 400) {
        int r = i / NODE_IN, k = i - r * NODE_IN;
        s[r][k] = nf[(v0 + r) * NODE_IN + k];
    }
    __syncthreads();
    int q = tid / 200;         // row group (0..1) -> rows q*16..q*16+15
    int c = tid - q * 200;
    int r0 = q * 16;
    ull acc[16];
#pragma unroll
    for (int r = 0; r < 16; r++) acc[r] = 0ull;
    const ull* Wp = g_Wnode + c;
    for (int k2 = 0; k2 < 37; k2++) {
        ull w = __ldg(&Wp[k2 * H]);
#pragma unroll
        for (int r = 0; r < 16; r++) {
            ull a = *(const ull*)&s[r0 + r][2 * k2];
            fma2(acc[r], a, w);
        }
    }
    float bb = __ldg(&b[c]);
#pragma unroll
    for (int r = 0; r < 16; r++) g_h[(size_t)(v0 + r0 + r) * H + c] = hsum2(acc[r]) + bb;
}

// ---------------- edge embedding: 400 threads, 2 row-groups x 200 cols ----------------
__global__ __launch_bounds__(400, 2) void k_edge_embed(const float* __restrict__ ef,
                                                       const float* __restrict__ b) {
    __shared__ __align__(16) float s[32][EDGE_IN];
    int e0 = blockIdx.x * 32;
    int tid = threadIdx.x;
    for (int i = tid; i < 32 * EDGE_IN; i += 400) {
        int r = i / EDGE_IN, k = i - r * EDGE_IN;
        s[r][k] = ef[(e0 + r) * EDGE_IN + k];
    }
    __syncthreads();
    int q = tid / 200;
    int c = tid - q * 200;
    int r0 = q * 16;
    ull acc[16];
#pragma unroll
    for (int r = 0; r < 16; r++) acc[r] = 0ull;
    const ull* Wp = g_Wedge + c;
#pragma unroll
    for (int k2 = 0; k2 < 6; k2++) {
        ull w = __ldg(&Wp[k2 * H]);
#pragma unroll
        for (int r = 0; r < 16; r++) {
            ull a = *(const ull*)&s[r0 + r][2 * k2];
            fma2(acc[r], a, w);
        }
    }
    float bb = __ldg(&b[c]);
#pragma unroll
    for (int r = 0; r < 16; r++) g_eh[(size_t)(e0 + r0 + r) * H + c] = hsum2(acc[r]) + bb;
}

// ---------------- fused layer: 800 threads = 4 row-groups x 200 cols ----------------
// block = 1 graph (32 nodes); each thread owns 8 rows of one column
__global__ __launch_bounds__(800, 2) void k_layer(const int* __restrict__ src,
                                                  const float* __restrict__ bias,
                                                  int layer) {
    extern __shared__ float smem[];
    float* s_h = smem;                       // [32][200]
    float* s_agg = s_h + NPG * H;            // [32][200]
    int* s_src = (int*)(s_agg + NPG * H);    // [128]

    int g = blockIdx.x;
    int tid = threadIdx.x;
    int vbase = g * NPG;

    // phase 1: stage h + src
    {
        const float4* gh4 = (const float4*)(g_h + (size_t)vbase * H);
        float4* sh4 = (float4*)s_h;
#pragma unroll
        for (int i = 0; i < 2; i++) sh4[tid + i * 800] = gh4[tid + i * 800];
        if (tid < NPG * DEG) s_src[tid] = src[vbase * DEG + tid] - vbase;
    }
    __syncthreads();

    int q = tid / 200;        // row group
    int c = tid - q * 200;    // column

    // phase 2: edge softmax + aggregation; thread (q,c) handles rows q,q+4,...,q+28
    {
        const float* ehb = g_eh + (size_t)vbase * DEG * H + c;
#pragma unroll
        for (int j = 0; j < 8; j++) {
            int v = q + 4 * j;
            int e0 = v * DEG;
            float m0 = s_h[s_src[e0 + 0] * H + c] + __ldg(&ehb[(e0 + 0) * H]);
            float m1 = s_h[s_src[e0 + 1] * H + c] + __ldg(&ehb[(e0 + 1) * H]);
            float m2 = s_h[s_src[e0 + 2] * H + c] + __ldg(&ehb[(e0 + 2) * H]);
            float m3 = s_h[s_src[e0 + 3] * H + c] + __ldg(&ehb[(e0 + 3) * H]);
            float mx = fmaxf(fmaxf(m0, m1), fmaxf(m2, m3));
            float e0x = __expf(m0 - mx), e1x = __expf(m1 - mx);
            float e2x = __expf(m2 - mx), e3x = __expf(m3 - mx);
            float den = e0x + e1x + e2x + e3x;
            float agg = m0 * e0x + m1 * e1x + m2 * e2x + m3 * e3x;
            s_agg[v * H + c] = agg / den;
        }
    }
    __syncthreads();

    // phase 3: D[r0..r0+8, c] = agg @ W via FFMA2, packed weights
    int r0 = q * 8;
    ull acc[8];
#pragma unroll
    for (int r = 0; r < 8; r++) acc[r] = 0ull;
    const ull* Wp = g_Wgnn + (size_t)layer * 100 * H + c;
    const float* ag = s_agg + r0 * H;
    for (int k = 0; k < H; k += 4) {
        int k2 = k >> 1;
        ull w01 = __ldg(&Wp[k2 * H]);
        ull w23 = __ldg(&Wp[(k2 + 1) * H]);
#pragma unroll
        for (int r = 0; r < 8; r++) {
            ulonglong2 a = *(const ulonglong2*)&ag[r * H + k];
            fma2(acc[r], a.x, w01);
            fma2(acc[r], a.y, w23);
        }
    }

    // phase 4: h = relu(D + bias) + h_old
    float bb = __ldg(&bias[c]);
#pragma unroll
    for (int r = 0; r < 8; r++) {
        float o = hsum2(acc[r]) + bb;
        o = o > 0.f ? o : 0.f;
        g_h[(size_t)(vbase + r0 + r) * H + c] = o + s_h[(r0 + r) * H + c];
    }
}

// ---------------- gf init ----------------
__global__ __launch_bounds__(200) void k_gf() {
    int g = blockIdx.x, c = threadIdx.x;
    float sum = 0.f;
    int base = g * NPG * H + c;
    for (int i = 0; i < NPG; i++) sum += g_h[base + i * H];
    g_gf[g * H + c] = sum;
}

// ---------------- readout attention ----------------
__global__ __launch_bounds__(256) void k_z(const float* __restrict__ lgW,
                                           const float* __restrict__ lgb, int t) {
    const float* w = lgW + t * H2;
    float bb = __ldg(&lgb[t]);
    int g = blockIdx.x;
    int tid = threadIdx.x;
    __shared__ float red[256];
    __shared__ float zs[NPG];

    float p = 0.f;
    if (tid < H) {
        float gfv = g_gf[g * H + tid];
        gfv = gfv > 0.f ? gfv : 0.f;
        p = gfv * w[tid];
    }
    red[tid] = p;
    __syncthreads();
    for (int off = 128; off > 0; off >>= 1) {
        if (tid < off) red[tid] += red[tid + off];
        __syncthreads();
    }
    float sg = red[0];

    int warp = tid >> 5, lane = tid & 31;
    for (int n = warp; n < NPG; n += 8) {
        int v = g * NPG + n;
        float sum = 0.f;
        for (int c = lane; c < H; c += 32) sum += g_h[v * H + c] * w[H + c];
        for (int off = 16; off; off >>= 1) sum += __shfl_xor_sync(0xffffffffu, sum, off);
        if (lane == 0) {
            float z = sum + sg + bb;
            zs[n] = z > 0.f ? z : 0.01f * z;
        }
    }
    __syncthreads();
    if (tid < 32) {
        float zv = zs[tid];
        float mx = zv;
        for (int off = 16; off; off >>= 1) mx = fmaxf(mx, __shfl_xor_sync(0xffffffffu, mx, off));
        float e = __expf(zv - mx);
        float den = e;
        for (int off = 16; off; off >>= 1) den += __shfl_xor_sync(0xffffffffu, den, off);
        g_a[g * NPG + tid] = e / den;
    }
}

// ---------------- hbar ----------------
__global__ __launch_bounds__(200) void k_hbar() {
    int g = blockIdx.x, c = threadIdx.x;
    float sum = 0.f;
    int vb = g * NPG;
    for (int i = 0; i < NPG; i++) sum += __ldg(&g_a[vb + i]) * g_h[(vb + i) * H + c];
    g_hbar[g * H + c] = sum;
}

// ---------------- ctx: 400 threads, 2 row-groups x 200 cols, 32 graphs/block ----------------
__global__ __launch_bounds__(400, 2) void k_ctx(const float* __restrict__ prb, int t) {
    __shared__ __align__(16) float s[32][H];
    int g0 = blockIdx.x * 32;
    int tid = threadIdx.x;
    for (int i = tid; i < 32 * H; i += 400) {
        int r = i / H, k = i - r * H;
        s[r][k] = g_hbar[(g0 + r) * H + k];
    }
    __syncthreads();
    int q = tid / 200;
    int c = tid - q * 200;
    int r0 = q * 16;
    ull acc[16];
#pragma unroll
    for (int r = 0; r < 16; r++) acc[r] = 0ull;
    const ull* Wp = g_Wpr + (size_t)t * 100 * H + c;
    for (int k = 0; k < H; k += 4) {
        int k2 = k >> 1;
        ull w01 = __ldg(&Wp[k2 * H]);
        ull w23 = __ldg(&Wp[(k2 + 1) * H]);
#pragma unroll
        for (int r = 0; r < 16; r++) {
            ulonglong2 a = *(const ulonglong2*)&s[r0 + r][k];
            fma2(acc[r], a.x, w01);
            fma2(acc[r], a.y, w23);
        }
    }
    float bb = __ldg(&prb[t * H + c]);
#pragma unroll
    for (int r = 0; r < 16; r++) {
        float o = hsum2(acc[r]) + bb;
        o = o > 0.f ? o : expm1f(o);
        g_ctx[(size_t)(g0 + r0 + r) * H + c] = o;
    }
}

// ---------------- GRU gate GEMMs: 8 graphs/block, 600 threads ----------------
__global__ __launch_bounds__(600) void k_gru(const float* __restrict__ bih,
                                             const float* __restrict__ bhh, int t) {
    __shared__ __align__(16) float sc[8][H];
    __shared__ __align__(16) float sh[8][H];
    int g0 = blockIdx.x * 8;
    int tid = threadIdx.x;
    for (int i = tid; i < 8 * H; i += 600) {
        int r = i / H, k = i - r * H;
        sc[r][k] = g_ctx[(g0 + r) * H + k];
        sh[r][k] = g_gf[(g0 + r) * H + k];
    }
    __syncthreads();
    int j = tid;
    const ull* Wi = g_Wih2 + (size_t)t * 100 * H3 + j;
    const ull* Wh = g_Whh2 + (size_t)t * 100 * H3 + j;
    ull ai[8], ah[8];
#pragma unroll
    for (int r = 0; r < 8; r++) { ai[r] = 0ull; ah[r] = 0ull; }
    for (int k = 0; k < H; k += 4) {
        int k2 = k >> 1;
        ull wi01 = __ldg(&Wi[k2 * H3]);
        ull wi23 = __ldg(&Wi[(k2 + 1) * H3]);
        ull wh01 = __ldg(&Wh[k2 * H3]);
        ull wh23 = __ldg(&Wh[(k2 + 1) * H3]);
#pragma unroll
        for (int r = 0; r < 8; r++) {
            ulonglong2 a = *(const ulonglong2*)&sc[r][k];
            fma2(ai[r], a.x, wi01);
            fma2(ai[r], a.y, wi23);
            ulonglong2 h4 = *(const ulonglong2*)&sh[r][k];
            fma2(ah[r], h4.x, wh01);
            fma2(ah[r], h4.y, wh23);
        }
    }
    float bi = __ldg(&bih[t * H3 + j]);
    float bh = __ldg(&bhh[t * H3 + j]);
#pragma unroll
    for (int r = 0; r < 8; r++) {
        g_gi[(size_t)(g0 + r) * H3 + j] = hsum2(ai[r]) + bi;
        g_gh[(size_t)(g0 + r) * H3 + j] = hsum2(ah[r]) + bh;
    }
}

// ---------------- GRU combine ----------------
__global__ __launch_bounds__(200) void k_gate() {
    int g = blockIdx.x, c = threadIdx.x;
    int base = g * H3;
    float ir = g_gi[base + c],          hr = g_gh[base + c];
    float iz = g_gi[base + H + c],      hz = g_gh[base + H + c];
    float in_ = g_gi[base + 2 * H + c], hn = g_gh[base + 2 * H + c];
    float r = 1.f / (1.f + expf(-(ir + hr)));
    float u = 1.f / (1.f + expf(-(iz + hz)));
    float n = tanhf(in_ + r * hn);
    int o = g * H + c;
    g_gf[o] = (1.f - u) * n + u * g_gf[o];
}

// ---------------- copy result ----------------
__global__ void k_copy(float* __restrict__ out, int n) {
    int i = blockIdx.x * blockDim.x + threadIdx.x;
    if (i < n) out[i] = g_gf[i];
}

// ---------------- launcher ----------------
extern "C" void kernel_launch(void* const* d_in, const int* in_sizes, int n_in,
                              void* d_out, int out_size) {
    const float* node_feat = (const float*)d_in[0];
    const float* edge_feat = (const float*)d_in[1];
    const int*   src       = (const int*)d_in[2];
    const float* node_W = (const float*)d_in[5];
    const float* node_b = (const float*)d_in[6];
    const float* edge_W = (const float*)d_in[7];
    const float* edge_b = (const float*)d_in[8];
    const float* gnn_W  = (const float*)d_in[9];
    const float* gnn_b  = (const float*)d_in[10];
    const float* lg_W   = (const float*)d_in[11];
    const float* lg_b   = (const float*)d_in[12];
    const float* pr_W   = (const float*)d_in[13];
    const float* pr_b   = (const float*)d_in[14];
    const float* W_ih   = (const float*)d_in[15];
    const float* W_hh   = (const float*)d_in[16];
    const float* b_ih   = (const float*)d_in[17];
    const float* b_hh   = (const float*)d_in[18];

    const int SMEM_LAYER = (2 * NPG * H + NPG * DEG) * 4;  // ~52KB
    cudaFuncSetAttribute(k_layer, cudaFuncAttributeMaxDynamicSharedMemorySize, SMEM_LAYER);

    ull* d_Wgnn;  cudaGetSymbolAddress((void**)&d_Wgnn, g_Wgnn);
    ull* d_Wpr;   cudaGetSymbolAddress((void**)&d_Wpr, g_Wpr);
    ull* d_Wnode; cudaGetSymbolAddress((void**)&d_Wnode, g_Wnode);
    ull* d_Wedge; cudaGetSymbolAddress((void**)&d_Wedge, g_Wedge);

    // pack weights
    k_packW<<<(NLAYERS * 100 * H + 255) / 256, 256>>>(gnn_W, d_Wgnn, NLAYERS * 100, H);
    k_packW<<<(TT * 100 * H + 255) / 256, 256>>>(pr_W, d_Wpr, TT * 100, H);
    k_packW<<<(37 * H + 255) / 256, 256>>>(node_W, d_Wnode, 37, H);
    k_packW<<<(6 * H + 255) / 256, 256>>>(edge_W, d_Wedge, 6, H);
    k_packGRU<<<(TT * 100 * H3 + 255) / 256, 256>>>(W_ih, W_hh);

    k_node_embed<<<Vn / 32, 400>>>(node_feat, node_b);
    k_edge_embed<<<En / 32, 400>>>(edge_feat, edge_b);

    for (int i = 0; i < NLAYERS; i++) {
        k_layer<<<Gn, 800, SMEM_LAYER>>>(src, gnn_b + i * H, i);
    }

    k_gf<<<Gn, 200>>>();
    for (int t = 0; t < TT; t++) {
        k_z<<<Gn, 256>>>(lg_W, lg_b, t);
        k_hbar<<<Gn, 200>>>();
        k_ctx<<<Gn / 32, 400>>>(pr_b, t);
        k_gru<<<Gn / 8, 600>>>(b_ih, b_hh, t);
        k_gate<<<Gn, 200>>>();
    }

    k_copy<<<(Gn * H + 255) / 256, 256>>>((float*)d_out, Gn * H);
}